// round 15
// baseline (speedup 1.0000x reference)
#include <cuda_runtime.h>

// x is [B=8, S=4096, D=1024] fp32; out[b,s,d] = x[b,s,d] + PE[s,d].
// PE[s,d] = sin(s / 10000^(j/1024)) for even d (j=d), cos(...) for odd d (j=d-1).
//
// R15 probe: same stream shape as the 6x-verified 38.5us kernel (one batch x
// 8 consecutive rows per block, .cs both directions, rotation-amortized
// sincos) but with sm_100a 256-bit ld/st.global.v8.f32 accesses:
// 128 threads/block, each thread owns 8 consecutive floats per row.
#define PE_S 4096
#define PE_D 1024
#define PE_B 8
#define ROWS_PER_BLOCK 8
#define CHUNK 4
#define F8_PER_ROW (PE_D / 8)                  // 128
#define GRID_BLOCKS ((PE_S / ROWS_PER_BLOCK) * PE_B)   // 4096

// 256-bit global load/store with streaming (.cs) policy — sm_100a feature.
__device__ __forceinline__ void ldg_v8_cs(const float* p, float v[8]) {
    asm volatile("ld.global.cs.v8.f32 {%0,%1,%2,%3,%4,%5,%6,%7}, [%8];"
        : "=f"(v[0]), "=f"(v[1]), "=f"(v[2]), "=f"(v[3]),
          "=f"(v[4]), "=f"(v[5]), "=f"(v[6]), "=f"(v[7])
        : "l"(p));
}
__device__ __forceinline__ void stg_v8_cs(float* p, const float v[8]) {
    asm volatile("st.global.cs.v8.f32 [%0], {%1,%2,%3,%4,%5,%6,%7,%8};"
        :: "l"(p),
           "f"(v[0]), "f"(v[1]), "f"(v[2]), "f"(v[3]),
           "f"(v[4]), "f"(v[5]), "f"(v[6]), "f"(v[7])
        : "memory");
}

// Accurate base sincos: reduce fp32 angle mod 2pi in double, sinf/cosf on the
// small remainder (safe under --use_fast_math). Once per thread per pair.
__device__ __forceinline__ void acc_sincos(float angle, float& s_out, float& c_out) {
    double a = (double)angle;
    double k = rint(a * 0.15915494309189535);          // 1/(2*pi)
    float r = (float)(a - k * 6.283185307179586);      // |r| <= pi
    s_out = sinf(r);
    c_out = cosf(r);
}

__global__ void __launch_bounds__(128)
pe_add_kernel(const float* __restrict__ x, float* __restrict__ out) {
    // blockIdx.x = b * 512 + rg
    int b  = blockIdx.x >> 9;                  // batch 0..7
    int rg = blockIdx.x & 511;                 // row group 0..511
    int s0 = rg << 3;                          // first of 8 consecutive rows
    int c  = threadIdx.x;                      // float8 column index 0..127

    // Thread owns columns 8c..8c+7 -> 4 frequency pairs at
    // j_even = 8c, 8c+2, 8c+4, 8c+6; p_k = 2^((8c+2k) * log2(1e4)/1024).
    const float L = 0.012976281620653759f;     // log2(10000)/1024
    float base_e = (float)(8 * c) * L;

    float sn[4], cs[4], cw[4], sw[4];
    float fs = (float)s0;
#pragma unroll
    for (int k = 0; k < 4; k++) {
        float p = exp2f(fmaf((float)(2 * k), L, base_e));
        acc_sincos(fs / p, sn[k], cs[k]);      // base PE at row s0
        float d = 1.0f / p;                    // per-row angle increment
        cw[k] = cosf(d);
        sw[k] = sinf(d);
    }

    const float* xp = x   + (((size_t)b * PE_S + s0) * PE_D) + (size_t)c * 8;
    float*       op = out + (((size_t)b * PE_S + s0) * PE_D) + (size_t)c * 8;

    // Two chunks of 4 rows: front-batch 4x 256-bit loads (128B in flight per
    // thread, matching the verified config), then add+store with rotation.
#pragma unroll
    for (int g = 0; g < ROWS_PER_BLOCK; g += CHUNK) {
        float v[CHUNK][8];
#pragma unroll
        for (int i = 0; i < CHUNK; i++) {
            ldg_v8_cs(xp + (size_t)(g + i) * PE_D, v[i]);
        }
#pragma unroll
        for (int i = 0; i < CHUNK; i++) {
            float o[8];
#pragma unroll
            for (int k = 0; k < 4; k++) {
                o[2 * k]     = v[i][2 * k]     + sn[k];   // even col -> sin
                o[2 * k + 1] = v[i][2 * k + 1] + cs[k];   // odd col  -> cos
            }
            stg_v8_cs(op + (size_t)(g + i) * PE_D, o);

            // Rotate each pair: sin(a+d)=s*cd+c*sd, cos(a+d)=c*cd-s*sd
#pragma unroll
            for (int k = 0; k < 4; k++) {
                float ns = fmaf(sn[k], cw[k],  cs[k] * sw[k]);
                float nc = fmaf(cs[k], cw[k], -sn[k] * sw[k]);
                sn[k] = ns; cs[k] = nc;
            }
        }
    }
}

extern "C" void kernel_launch(void* const* d_in, const int* in_sizes, int n_in,
                              void* d_out, int out_size) {
    (void)in_sizes; (void)n_in; (void)out_size;
    const float* x = (const float*)d_in[0];
    float* out = (float*)d_out;

    pe_add_kernel<<<GRID_BLOCKS, 128>>>(x, out);
}

// round 16
// speedup vs baseline: 1.0152x; 1.0152x over previous
#include <cuda_runtime.h>

// x is [B=8, S=4096, D=1024] fp32; out[b,s,d] = x[b,s,d] + PE[s,d].
// PE[s,d] = sin(s / 10000^(j/1024)) for even d (j=d), cos(...) for odd d (j=d-1).
//
// FINAL kernel — best of 8 measured variants; verified SIX times at
// 38.50-38.88us kernel (6.95 TB/s app throughput, ~87% of HBM spec),
// rel_err 1.95e-5 every run. Closed axes (all measured): work mapping,
// per-thread MLP, stream length, occupancy, launch structure, load policy,
// store policy (__stwt neutral), access width (v8.f32 regressed to 41.6us).
//  - single fused launch, PE computed in-kernel (exp2f powers)
//  - block = one batch x 8 consecutive rows -> contiguous 32KB rd + 32KB wr
//  - one accurate double-reduced sincos per thread, rotated across 8 rows
//  - 8 front-batched LDG.128 (MLP=8) then 8 STG.128, both with .cs hints
#define PE_S 4096
#define PE_D 1024
#define PE_B 8
#define ROWS_PER_BLOCK 8
#define F4_PER_ROW (PE_D / 4)                 // 256
#define GRID_BLOCKS ((PE_S / ROWS_PER_BLOCK) * PE_B)   // 4096

// Accurate base sincos: reduce fp32 angle mod 2pi in double, sinf/cosf on the
// small remainder (safe under --use_fast_math). Used once per thread.
__device__ __forceinline__ void acc_sincos(float angle, float& s_out, float& c_out) {
    double a = (double)angle;
    double k = rint(a * 0.15915494309189535);          // 1/(2*pi)
    float r = (float)(a - k * 6.283185307179586);      // |r| <= pi
    s_out = sinf(r);
    c_out = cosf(r);
}

__global__ void __launch_bounds__(256)
pe_add_kernel(const float4* __restrict__ x, float4* __restrict__ out) {
    // blockIdx.x = b * 512 + rg
    int b  = blockIdx.x >> 9;                  // batch 0..7
    int rg = blockIdx.x & 511;                 // row group 0..511
    int s0 = rg << 3;                          // first of 8 consecutive rows
    int c  = threadIdx.x;                      // float4 column index 0..255

    // Frequencies for columns 4c..4c+3:
    //   pair 0: p0 = 10000^(4c/1024) = 2^(c*K),  pair 1: p1 = 2^(c*K + C)
    const float K = 0.051905126482615075f;     // log2(10000)/256
    const float C = 0.025952563241307537f;     // log2(10000)/512
    float fc = (float)c;
    float p0 = exp2f(fc * K);
    float p1 = exp2f(fmaf(fc, K, C));

    // Base PE at row s0 (accurate), matching reference fp32 s/p division.
    float fs = (float)s0;
    float sn0, cs0, sn1, cs1;
    acc_sincos(fs / p0, sn0, cs0);
    acc_sincos(fs / p1, sn1, cs1);

    // Per-row angle increments delta = 1/p (<= 1 rad, no reduction needed).
    float d0 = 1.0f / p0, d1 = 1.0f / p1;
    float cw0 = cosf(d0), sw0 = sinf(d0);
    float cw1 = cosf(d1), sw1 = sinf(d1);

    // Front-batch all 8 row loads: contiguous 32KB per block (MLP=8/thread).
    size_t base = ((size_t)b * PE_S + s0) * F4_PER_ROW + c;
    float4 v[ROWS_PER_BLOCK];
#pragma unroll
    for (int i = 0; i < ROWS_PER_BLOCK; i++) {
        v[i] = __ldcs(&x[base + (size_t)i * F4_PER_ROW]);
    }

    // Add PE and store; rotate (sn,cs) by delta between rows.
#pragma unroll
    for (int i = 0; i < ROWS_PER_BLOCK; i++) {
        float4 o;
        o.x = v[i].x + sn0;   // even col -> sin
        o.y = v[i].y + cs0;   // odd col  -> cos
        o.z = v[i].z + sn1;
        o.w = v[i].w + cs1;
        __stcs(&out[base + (size_t)i * F4_PER_ROW], o);

        // sin(a+d) = sin a * cos d + cos a * sin d
        // cos(a+d) = cos a * cos d - sin a * sin d
        float ns0 = fmaf(sn0, cw0,  cs0 * sw0);
        float nc0 = fmaf(cs0, cw0, -sn0 * sw0);
        float ns1 = fmaf(sn1, cw1,  cs1 * sw1);
        float nc1 = fmaf(cs1, cw1, -sn1 * sw1);
        sn0 = ns0; cs0 = nc0; sn1 = ns1; cs1 = nc1;
    }
}

extern "C" void kernel_launch(void* const* d_in, const int* in_sizes, int n_in,
                              void* d_out, int out_size) {
    (void)in_sizes; (void)n_in; (void)out_size;
    const float4* x = (const float4*)d_in[0];
    float4* out = (float4*)d_out;

    pe_add_kernel<<<GRID_BLOCKS, 256>>>(x, out);
}

// round 17
// speedup vs baseline: 1.0279x; 1.0126x over previous
#include <cuda_runtime.h>

// x is [B=8, S=4096, D=1024] fp32; out[b,s,d] = x[b,s,d] + PE[s,d].
// PE[s,d] = sin(s / 10000^(j/1024)) for even d (j=d), cos(...) for odd d (j=d-1).
//
// FINAL kernel — best of 8 measured variants; verified SEVEN times at
// 38.50-38.88us kernel (6.95 TB/s app throughput, ~87% of HBM spec),
// rel_err 1.95e-5 every run. Closed axes (all measured): work mapping,
// per-thread MLP, stream length, occupancy, launch structure, load policy,
// store policy (__stwt neutral), access width (v8.f32 regressed to 41.6us).
//  - single fused launch, PE computed in-kernel (exp2f powers)
//  - block = one batch x 8 consecutive rows -> contiguous 32KB rd + 32KB wr
//  - one accurate double-reduced sincos per thread, rotated across 8 rows
//  - 8 front-batched LDG.128 (MLP=8) then 8 STG.128, both with .cs hints
#define PE_S 4096
#define PE_D 1024
#define PE_B 8
#define ROWS_PER_BLOCK 8
#define F4_PER_ROW (PE_D / 4)                 // 256
#define GRID_BLOCKS ((PE_S / ROWS_PER_BLOCK) * PE_B)   // 4096

// Accurate base sincos: reduce fp32 angle mod 2pi in double, sinf/cosf on the
// small remainder (safe under --use_fast_math). Used once per thread.
__device__ __forceinline__ void acc_sincos(float angle, float& s_out, float& c_out) {
    double a = (double)angle;
    double k = rint(a * 0.15915494309189535);          // 1/(2*pi)
    float r = (float)(a - k * 6.283185307179586);      // |r| <= pi
    s_out = sinf(r);
    c_out = cosf(r);
}

__global__ void __launch_bounds__(256)
pe_add_kernel(const float4* __restrict__ x, float4* __restrict__ out) {
    // blockIdx.x = b * 512 + rg
    int b  = blockIdx.x >> 9;                  // batch 0..7
    int rg = blockIdx.x & 511;                 // row group 0..511
    int s0 = rg << 3;                          // first of 8 consecutive rows
    int c  = threadIdx.x;                      // float4 column index 0..255

    // Frequencies for columns 4c..4c+3:
    //   pair 0: p0 = 10000^(4c/1024) = 2^(c*K),  pair 1: p1 = 2^(c*K + C)
    const float K = 0.051905126482615075f;     // log2(10000)/256
    const float C = 0.025952563241307537f;     // log2(10000)/512
    float fc = (float)c;
    float p0 = exp2f(fc * K);
    float p1 = exp2f(fmaf(fc, K, C));

    // Base PE at row s0 (accurate), matching reference fp32 s/p division.
    float fs = (float)s0;
    float sn0, cs0, sn1, cs1;
    acc_sincos(fs / p0, sn0, cs0);
    acc_sincos(fs / p1, sn1, cs1);

    // Per-row angle increments delta = 1/p (<= 1 rad, no reduction needed).
    float d0 = 1.0f / p0, d1 = 1.0f / p1;
    float cw0 = cosf(d0), sw0 = sinf(d0);
    float cw1 = cosf(d1), sw1 = sinf(d1);

    // Front-batch all 8 row loads: contiguous 32KB per block (MLP=8/thread).
    size_t base = ((size_t)b * PE_S + s0) * F4_PER_ROW + c;
    float4 v[ROWS_PER_BLOCK];
#pragma unroll
    for (int i = 0; i < ROWS_PER_BLOCK; i++) {
        v[i] = __ldcs(&x[base + (size_t)i * F4_PER_ROW]);
    }

    // Add PE and store; rotate (sn,cs) by delta between rows.
#pragma unroll
    for (int i = 0; i < ROWS_PER_BLOCK; i++) {
        float4 o;
        o.x = v[i].x + sn0;   // even col -> sin
        o.y = v[i].y + cs0;   // odd col  -> cos
        o.z = v[i].z + sn1;
        o.w = v[i].w + cs1;
        __stcs(&out[base + (size_t)i * F4_PER_ROW], o);

        // sin(a+d) = sin a * cos d + cos a * sin d
        // cos(a+d) = cos a * cos d - sin a * sin d
        float ns0 = fmaf(sn0, cw0,  cs0 * sw0);
        float nc0 = fmaf(cs0, cw0, -sn0 * sw0);
        float ns1 = fmaf(sn1, cw1,  cs1 * sw1);
        float nc1 = fmaf(cs1, cw1, -sn1 * sw1);
        sn0 = ns0; cs0 = nc0; sn1 = ns1; cs1 = nc1;
    }
}

extern "C" void kernel_launch(void* const* d_in, const int* in_sizes, int n_in,
                              void* d_out, int out_size) {
    (void)in_sizes; (void)n_in; (void)out_size;
    const float4* x = (const float4*)d_in[0];
    float4* out = (float4*)d_out;

    pe_add_kernel<<<GRID_BLOCKS, 256>>>(x, out);
}